// round 6
// baseline (speedup 1.0000x reference)
#include <cuda_runtime.h>
#include <math.h>

// gdfn_region_batch: single persistent fused kernel, low-smem variant.
// img_3d is NOT materialized; phase 3 recomputes the one selected window
// weight per pixel (3 exps) instead of storing all 9 (41.6 KB smem saved).
// smem = 27.7 KB -> 8 CTAs/SM -> 100% occupancy.

#define BATCH 8
#define CH 3
#define HH 512
#define WW 512
#define HP 514
#define TS 32
#define PR 38          // TS + 6
#define E2 36          // TS + 4
#define E1 34          // TS + 2
#define NTHREADS 256
#define NTILES 2048
#define GRIDSZ 1216    // 8 CTAs/SM * 152 SMs -> one wave

#define SP_SIZE   (CH*PR*PR)   // 4332
#define SR_SIZE   (E2*E2)      // 1296
#define SMOD_SIZE (E2*E2)      // 1296
#define SMEM_FLOATS (SP_SIZE + SR_SIZE + SMOD_SIZE)  // 6924 floats = 27696 B

__global__ __launch_bounds__(NTHREADS)
void gdfn_fused_kernel(const float* __restrict__ img,
                       const float* __restrict__ noise,
                       const float* __restrict__ re_mask,
                       const int*   __restrict__ sel,
                       const int*   __restrict__ mix_sel,
                       float* __restrict__ out)
{
    const int tid = threadIdx.x;

    extern __shared__ float smem[];
    float* sp   = smem;                    // [CH][PR][PR] img_p = pad(img)+noise
    float* sr   = sp + SP_SIZE;            // [E2][E2]     img_r
    float* smod = sr + SR_SIZE;            // [E2][E2]     img_3d_mod

    for (int tile = blockIdx.x; tile < NTILES; tile += GRIDSZ) {
        const int b  = tile >> 8;
        const int h0 = ((tile >> 4) & 15) * TS;
        const int w0 = (tile & 15) * TS;

        const bool apply = (sel[b] != 0);

        // ---- mask scan ------------------------------------------------------
        int local_ok = 1;
        if (apply) {
            for (int i = tid; i < CH * TS * (TS / 4); i += NTHREADS) {
                int c   = i / (TS * TS / 4);
                int rem = i % (TS * TS / 4);
                int r   = rem / (TS / 4);
                int q   = rem % (TS / 4);
                size_t base = (((size_t)b * CH + c) * HH + (h0 + r)) * WW + w0 + q * 4;
                float4 rm = *(const float4*)(re_mask + base);
                if (rm.x != 1.0f || rm.y != 1.0f || rm.z != 1.0f || rm.w != 1.0f)
                    local_ok = 0;
            }
        }
        // Barrier also separates prev tile's phase-4 smem reads from the
        // phase-1 smem writes below.
        int allone = __syncthreads_and(local_ok);
        bool heavy = apply && !allone;

        if (!heavy) {
            for (int i = tid; i < CH * TS * (TS / 4); i += NTHREADS) {
                int c   = i / (TS * TS / 4);
                int rem = i % (TS * TS / 4);
                int r   = rem / (TS / 4);
                int q   = rem % (TS / 4);
                size_t base = (((size_t)b * CH + c) * HH + (h0 + r)) * WW + w0 + q * 4;
                *(float4*)(out + base) = *(const float4*)(img + base);
            }
            continue;
        }

        // ---- heavy path -----------------------------------------------------
        // Phase 1: img_p region
        for (int i = tid; i < CH * PR * PR; i += NTHREADS) {
            int c   = i / (PR * PR);
            int rem = i % (PR * PR);
            int py  = rem / PR, px = rem % PR;
            int y = h0 - 2 + py;
            int x = w0 - 2 + px;
            float v = 0.0f;
            if (y >= 0 && y < HP && x >= 0 && x < HP) {
                v = noise[(((size_t)b * CH + c) * HP + y) * HP + x];
                int iy = y - 1, ix = x - 1;
                if (iy >= 0 && iy < HH && ix >= 0 && ix < WW)
                    v += img[(((size_t)b * CH + c) * HH + iy) * WW + ix];
            }
            sp[(c * PR + py) * PR + px] = v;
        }
        __syncthreads();

        const bool mix = (mix_sel[b] != 0);

        // Phase 2: img_r on E2 x E2 (img_3d NOT stored)
        for (int p = tid; p < E2 * E2; p += NTHREADS) {
            int r  = p / E2, cc = p % E2;
            int gy = h0 - 2 + r, gx = w0 - 2 + cc;
            float img_r = 0.0f;
            if (gy >= 0 && gy < HH && gx >= 0 && gx < WW) {
                float m[9], vsum[9];
                #pragma unroll
                for (int k = 0; k < 9; k++) { m[k] = 3.4e38f; vsum[k] = 0.0f; }
                #pragma unroll
                for (int c = 0; c < CH; c++) {
                    float v[9]; float s = 0.0f;
                    #pragma unroll
                    for (int i = 0; i < 3; i++)
                        #pragma unroll
                        for (int j = 0; j < 3; j++) {
                            float tv = sp[(c * PR + r + i) * PR + cc + j];
                            v[i * 3 + j] = tv; s += tv; vsum[i * 3 + j] += tv;
                        }
                    float mean = s * (1.0f / 9.0f);
                    float sd2 = 0.0f;
                    #pragma unroll
                    for (int k = 0; k < 9; k++) {
                        float d = v[k] - mean; v[k] = d; sd2 += d * d;
                    }
                    float inv = __fdividef(4.0f, sd2);   // 1/(2*var_ddof1)
                    #pragma unroll
                    for (int k = 0; k < 9; k++) {
                        float wv = __expf(-v[k] * v[k] * inv);
                        m[k] = fminf(m[k], wv);
                    }
                }
                float num = 0.0f, den = 0.0f;
                #pragma unroll
                for (int k = 0; k < 9; k++) { num += m[k] * vsum[k]; den += m[k]; }
                img_r = __fdividef(num, den);
            }
            sr[r * E2 + cc] = img_r;
        }
        __syncthreads();

        // Phase 3: argmin/argmax of img_r 3x3 (first-index tie-break);
        // recompute the selected window weight m[id] (3 exps, bit-identical
        // to the value phase 2 would have stored).
        for (int p = tid; p < E1 * E1; p += NTHREADS) {
            int r  = 1 + p / E1, cc = 1 + p % E1;
            int gy = h0 - 2 + r, gx = w0 - 2 + cc;
            float mv = 0.0f;
            if (gy >= 0 && gy < HH && gx >= 0 && gx < WW) {
                float bmin = 3.4e38f, bmax = -3.4e38f;
                int kmin = 0, kmax = 0;
                #pragma unroll
                for (int i = 0; i < 3; i++)
                    #pragma unroll
                    for (int j = 0; j < 3; j++) {
                        float val = sr[(r - 1 + i) * E2 + (cc - 1 + j)];
                        int k = i * 3 + j;
                        if (val < bmin) { bmin = val; kmin = k; }
                        if (val > bmax) { bmax = val; kmax = k; }
                    }
                int id = mix ? kmax : kmin;
                int di = id / 3, dj = id % 3;
                mv = 3.4e38f;
                #pragma unroll
                for (int c = 0; c < CH; c++) {
                    float v[9]; float s = 0.0f;
                    #pragma unroll
                    for (int i = 0; i < 3; i++)
                        #pragma unroll
                        for (int j = 0; j < 3; j++) {
                            float tv = sp[(c * PR + r + i) * PR + cc + j];
                            v[i * 3 + j] = tv; s += tv;
                        }
                    float mean = s * (1.0f / 9.0f);
                    float sd2 = 0.0f;
                    #pragma unroll
                    for (int k = 0; k < 9; k++) {
                        float d = v[k] - mean; v[k] = d; sd2 += d * d;
                    }
                    float inv = __fdividef(4.0f, sd2);
                    float dsel = v[di * 3 + dj];
                    float wv = __expf(-dsel * dsel * inv);
                    mv = fminf(mv, wv);
                }
            }
            smod[r * E2 + cc] = mv;
        }
        __syncthreads();

        // Phase 4: img_mod and final compose
        for (int p = tid; p < TS * TS; p += NTHREADS) {
            int ty = p / TS, tx = p % TS;
            int gy = h0 + ty, gx = w0 + tx;
            float mm[9]; float den = 0.0f;
            #pragma unroll
            for (int i = 0; i < 3; i++)
                #pragma unroll
                for (int j = 0; j < 3; j++) {
                    float tv = smod[(ty + 1 + i) * E2 + (tx + 1 + j)];
                    mm[i * 3 + j] = tv; den += tv;
                }
            float rden = __fdividef(1.0f, den);
            #pragma unroll
            for (int c = 0; c < CH; c++) {
                float num = 0.0f;
                #pragma unroll
                for (int i = 0; i < 3; i++)
                    #pragma unroll
                    for (int j = 0; j < 3; j++)
                        num += sp[(c * PR + ty + 2 + i) * PR + tx + 2 + j] * mm[i * 3 + j];
                float imod = num * rden;
                size_t gidx = (((size_t)b * CH + c) * HH + gy) * WW + gx;
                float im = img[gidx];
                float re = re_mask[gidx];
                out[gidx] = imod * (1.0f - re) + im * re;  // exact where re==1
            }
        }
    }
}

extern "C" void kernel_launch(void* const* d_in, const int* in_sizes, int n_in,
                              void* d_out, int out_size)
{
    const float* img     = (const float*)d_in[0];
    const float* noise   = (const float*)d_in[1];
    const float* re_mask = (const float*)d_in[2];
    const int*   sel     = (const int*)d_in[3];
    const int*   mix_sel = (const int*)d_in[4];
    float* out = (float*)d_out;

    size_t smem = SMEM_FLOATS * sizeof(float);
    cudaFuncSetAttribute(gdfn_fused_kernel,
                         cudaFuncAttributeMaxDynamicSharedMemorySize, (int)smem);

    gdfn_fused_kernel<<<GRIDSZ, NTHREADS, smem>>>(img, noise, re_mask, sel,
                                                  mix_sel, out);
}

// round 8
// speedup vs baseline: 1.1480x; 1.1480x over previous
#include <cuda_runtime.h>
#include <math.h>

// gdfn_region_batch: single persistent kernel, 16x16 tiles.
// Small tiles quarter the per-heavy-tile latency and spread heavy work over
// ~4x more blocks, shrinking the low-occupancy tail that dominated R5/R6.
// smem = 9.0 KB; grid = 760 = 5 CTA/SM * 152 SMs (one wave at regs=48).

#define BATCH 8
#define CH 3
#define HH 512
#define WW 512
#define HP 514
#define TS 16
#define PR 22          // TS + 6
#define E2 20          // TS + 4
#define E1 18          // TS + 2
#define NTHREADS 256
#define TPB 32         // tiles per image row/col
#define NTILES (BATCH*TPB*TPB)   // 8192
#define GRIDSZ 760     // 5 CTA/SM * 152 SM

#define SP_SIZE   (CH*PR*PR)   // 1452
#define SR_SIZE   (E2*E2)      // 400
#define SMOD_SIZE (E2*E2)      // 400
#define SMEM_FLOATS (SP_SIZE + SR_SIZE + SMOD_SIZE)  // 2252 floats = 9008 B

#define NV4 (CH*TS*TS/4)       // 192 float4 per tile

__global__ __launch_bounds__(NTHREADS)
void gdfn_fused_kernel(const float* __restrict__ img,
                       const float* __restrict__ noise,
                       const float* __restrict__ re_mask,
                       const int*   __restrict__ sel,
                       const int*   __restrict__ mix_sel,
                       float* __restrict__ out)
{
    const int tid = threadIdx.x;

    extern __shared__ float smem[];
    float* sp   = smem;                    // [CH][PR][PR] img_p = pad(img)+noise
    float* sr   = sp + SP_SIZE;            // [E2][E2]     img_r
    float* smod = sr + SR_SIZE;            // [E2][E2]     img_3d_mod

    for (int tile = blockIdx.x; tile < NTILES; tile += GRIDSZ) {
        const int b  = tile >> 10;
        const int h0 = ((tile >> 5) & 31) * TS;
        const int w0 = (tile & 31) * TS;

        const bool apply = (sel[b] != 0);

        // ---- mask scan + img prefetch (one float4 per thread, 192 active) --
        const bool act = (tid < NV4);
        size_t base = 0;
        float4 iv = make_float4(0.f, 0.f, 0.f, 0.f);
        int local_ok = 1;
        if (act) {
            int c   = tid >> 6;          // /64
            int rem = tid & 63;
            int r   = rem >> 2;
            int q   = rem & 3;
            base = (((size_t)b * CH + c) * HH + (h0 + r)) * WW + w0 + q * 4;
            iv = *(const float4*)(img + base);       // copy payload (in flight)
            if (apply) {
                float4 rm = *(const float4*)(re_mask + base);
                if (rm.x != 1.0f || rm.y != 1.0f || rm.z != 1.0f || rm.w != 1.0f)
                    local_ok = 0;
            }
        }
        // Barrier also separates prev tile's phase-4 smem reads from the
        // phase-1 smem writes below.
        int allone = __syncthreads_and(local_ok);
        bool heavy = apply && !allone;

        if (!heavy) {
            if (act) *(float4*)(out + base) = iv;    // out == img exactly here
            continue;
        }

        // ---- heavy path -----------------------------------------------------
        // Phase 1: img_p region (pad(img)+noise) into sp
        for (int i = tid; i < CH * PR * PR; i += NTHREADS) {
            int c   = i / (PR * PR);
            int rem = i % (PR * PR);
            int py  = rem / PR, px = rem % PR;
            int y = h0 - 2 + py;
            int x = w0 - 2 + px;
            float v = 0.0f;
            if (y >= 0 && y < HP && x >= 0 && x < HP) {
                v = noise[(((size_t)b * CH + c) * HP + y) * HP + x];
                int iy = y - 1, ix = x - 1;
                if (iy >= 0 && iy < HH && ix >= 0 && ix < WW)
                    v += img[(((size_t)b * CH + c) * HH + iy) * WW + ix];
            }
            sp[(c * PR + py) * PR + px] = v;
        }
        __syncthreads();

        const bool mix = (mix_sel[b] != 0);

        // Phase 2: img_r on E2 x E2 (img_3d NOT stored; recomputed in ph.3)
        for (int p = tid; p < E2 * E2; p += NTHREADS) {
            int r  = p / E2, cc = p % E2;
            int gy = h0 - 2 + r, gx = w0 - 2 + cc;
            float img_r = 0.0f;
            if (gy >= 0 && gy < HH && gx >= 0 && gx < WW) {
                float m[9], vsum[9];
                #pragma unroll
                for (int k = 0; k < 9; k++) { m[k] = 3.4e38f; vsum[k] = 0.0f; }
                #pragma unroll
                for (int c = 0; c < CH; c++) {
                    float v[9]; float s = 0.0f;
                    #pragma unroll
                    for (int i = 0; i < 3; i++)
                        #pragma unroll
                        for (int j = 0; j < 3; j++) {
                            float tv = sp[(c * PR + r + i) * PR + cc + j];
                            v[i * 3 + j] = tv; s += tv; vsum[i * 3 + j] += tv;
                        }
                    float mean = s * (1.0f / 9.0f);
                    float sd2 = 0.0f;
                    #pragma unroll
                    for (int k = 0; k < 9; k++) {
                        float d = v[k] - mean; v[k] = d; sd2 += d * d;
                    }
                    float inv = __fdividef(4.0f, sd2);   // 1/(2*var_ddof1)
                    #pragma unroll
                    for (int k = 0; k < 9; k++) {
                        float wv = __expf(-v[k] * v[k] * inv);
                        m[k] = fminf(m[k], wv);
                    }
                }
                float num = 0.0f, den = 0.0f;
                #pragma unroll
                for (int k = 0; k < 9; k++) { num += m[k] * vsum[k]; den += m[k]; }
                img_r = __fdividef(num, den);
            }
            sr[r * E2 + cc] = img_r;
        }
        __syncthreads();

        // Phase 3: argmin/argmax of img_r 3x3 (first-index tie-break);
        // recompute the selected weight m[id] (bit-identical arithmetic).
        for (int p = tid; p < E1 * E1; p += NTHREADS) {
            int r  = 1 + p / E1, cc = 1 + p % E1;
            int gy = h0 - 2 + r, gx = w0 - 2 + cc;
            float mv = 0.0f;
            if (gy >= 0 && gy < HH && gx >= 0 && gx < WW) {
                float bmin = 3.4e38f, bmax = -3.4e38f;
                int kmin = 0, kmax = 0;
                #pragma unroll
                for (int i = 0; i < 3; i++)
                    #pragma unroll
                    for (int j = 0; j < 3; j++) {
                        float val = sr[(r - 1 + i) * E2 + (cc - 1 + j)];
                        int k = i * 3 + j;
                        if (val < bmin) { bmin = val; kmin = k; }
                        if (val > bmax) { bmax = val; kmax = k; }
                    }
                int id = mix ? kmax : kmin;
                int di = id / 3, dj = id % 3;
                mv = 3.4e38f;
                #pragma unroll
                for (int c = 0; c < CH; c++) {
                    float v[9]; float s = 0.0f;
                    #pragma unroll
                    for (int i = 0; i < 3; i++)
                        #pragma unroll
                        for (int j = 0; j < 3; j++) {
                            float tv = sp[(c * PR + r + i) * PR + cc + j];
                            v[i * 3 + j] = tv; s += tv;
                        }
                    float mean = s * (1.0f / 9.0f);
                    float sd2 = 0.0f;
                    #pragma unroll
                    for (int k = 0; k < 9; k++) {
                        float d = v[k] - mean; v[k] = d; sd2 += d * d;
                    }
                    float inv = __fdividef(4.0f, sd2);
                    float dsel = v[di * 3 + dj];
                    float wv = __expf(-dsel * dsel * inv);
                    mv = fminf(mv, wv);
                }
            }
            smod[r * E2 + cc] = mv;
        }
        __syncthreads();

        // Phase 4: img_mod and final compose (256 px = 1 per thread)
        {
            int p = tid;
            int ty = p >> 4, tx = p & 15;
            int gy = h0 + ty, gx = w0 + tx;
            float mm[9]; float den = 0.0f;
            #pragma unroll
            for (int i = 0; i < 3; i++)
                #pragma unroll
                for (int j = 0; j < 3; j++) {
                    float tv = smod[(ty + 1 + i) * E2 + (tx + 1 + j)];
                    mm[i * 3 + j] = tv; den += tv;
                }
            float rden = __fdividef(1.0f, den);
            #pragma unroll
            for (int c = 0; c < CH; c++) {
                float num = 0.0f;
                #pragma unroll
                for (int i = 0; i < 3; i++)
                    #pragma unroll
                    for (int j = 0; j < 3; j++)
                        num += sp[(c * PR + ty + 2 + i) * PR + tx + 2 + j] * mm[i * 3 + j];
                float imod = num * rden;
                size_t gidx = (((size_t)b * CH + c) * HH + gy) * WW + gx;
                float im = img[gidx];
                float re = re_mask[gidx];
                out[gidx] = imod * (1.0f - re) + im * re;  // exact where re==1
            }
        }
    }
}

extern "C" void kernel_launch(void* const* d_in, const int* in_sizes, int n_in,
                              void* d_out, int out_size)
{
    const float* img     = (const float*)d_in[0];
    const float* noise   = (const float*)d_in[1];
    const float* re_mask = (const float*)d_in[2];
    const int*   sel     = (const int*)d_in[3];
    const int*   mix_sel = (const int*)d_in[4];
    float* out = (float*)d_out;

    size_t smem = SMEM_FLOATS * sizeof(float);
    cudaFuncSetAttribute(gdfn_fused_kernel,
                         cudaFuncAttributeMaxDynamicSharedMemorySize, (int)smem);

    gdfn_fused_kernel<<<GRIDSZ, NTHREADS, smem>>>(img, noise, re_mask, sel,
                                                  mix_sel, out);
}